// round 11
// baseline (speedup 1.0000x reference)
#include <cuda_runtime.h>
#include <cuda_fp16.h>
#include <cstdint>

// ESMGridSample: bilinear grid_sample, zeros padding, align_corners=False.
// img:  [16, 1, 1024, 1024] f32   (d_in[0])
// grid: [16, 1024, 1024, 2] f32   (d_in[1])
// out:  [16, 1, 1024, 1024] f32
//
// R9: per-pixel 2x2 fp16 tiles (8 B, ONE LDG.64 per pixel) as in R7, plus:
//   - main: 8 px/thread in two software-pipelined groups of 4
//     (loads A, loads B, consume A, consume B), reg-capped to 6 CTAs/SM.
//   - prepass: 8 tiles/thread, 64 B contiguous stores, shfl for the edge
//     element, rows shared within a block (write-bandwidth-bound shape).

#define DIM 1024
#define TOTAL (16u * 1024u * 1024u)

__device__ __align__(16) uint2 g_tiles[16u * 1024u * 1024u];   // 128 MB

__global__ __launch_bounds__(256) void esm_prepass_kernel(
    const float* __restrict__ img)
{
    // Block = 2 image rows of one batch; 128 threads per row, 8 tiles each.
    unsigned blk = blockIdx.x;                 // 16 * 512 = 8192 blocks
    unsigned y0 = (blk & 511u) * 2u;
    unsigned b  = blk >> 9;
    unsigned t  = threadIdx.x;
    unsigned row = y0 + (t >> 7);              // y0 or y0+1 (warps don't split rows)
    unsigned x  = (t & 127u) * 8u;

    const float* base = img + ((size_t)b << 20);
    unsigned rown = min(row + 1u, 1023u);
    const float* rowA = base + ((size_t)row  << 10);
    const float* rowB = base + ((size_t)rown << 10);

    float4 a0 = __ldg((const float4*)(rowA + x));
    float4 a1 = __ldg((const float4*)(rowA + x + 4));
    float4 b0 = __ldg((const float4*)(rowB + x));
    float4 b1 = __ldg((const float4*)(rowB + x + 4));

    // Element x+8 = next lane's a0.x / b0.x; lane 31 loads it (clamped).
    unsigned lane = t & 31u;
    float ea = __shfl_down_sync(0xffffffffu, a0.x, 1);
    float eb = __shfl_down_sync(0xffffffffu, b0.x, 1);
    if (lane == 31u) {
        unsigned xe = min(x + 8u, 1023u);
        ea = __ldg(rowA + xe);
        eb = __ldg(rowB + xe);
    }

    float av[9] = {a0.x, a0.y, a0.z, a0.w, a1.x, a1.y, a1.z, a1.w, ea};
    float bv[9] = {b0.x, b0.y, b0.z, b0.w, b1.x, b1.y, b1.z, b1.w, eb};

    uint32_t w[16];
#pragma unroll
    for (int j = 0; j < 8; ++j) {
        __half2 h0 = __floats2half2_rn(av[j], av[j + 1]);
        __half2 h1 = __floats2half2_rn(bv[j], bv[j + 1]);
        w[2 * j]     = *(uint32_t*)&h0;
        w[2 * j + 1] = *(uint32_t*)&h1;
    }
    // 8 tiles = 64 B contiguous, 64 B aligned (x % 8 == 0).
    uint4* dst = (uint4*)(g_tiles + (((size_t)b << 20) | ((size_t)row << 10) | x));
    dst[0] = make_uint4(w[0],  w[1],  w[2],  w[3]);
    dst[1] = make_uint4(w[4],  w[5],  w[6],  w[7]);
    dst[2] = make_uint4(w[8],  w[9],  w[10], w[11]);
    dst[3] = make_uint4(w[12], w[13], w[14], w[15]);
}

// Group of 4: phase 1 (addresses + gathers), phase 2 (weights + interp).
__device__ __forceinline__ void issue4(
    const uint2* __restrict__ gb, float4 ga, float4 gc,
    float* ixs, float* iys, uint2* q)
{
    float xs[4] = {ga.x, ga.z, gc.x, gc.z};
    float ys[4] = {ga.y, ga.w, gc.y, gc.w};
#pragma unroll
    for (int i = 0; i < 4; ++i) {
        float ix = fmaf(xs[i], 512.0f, 511.5f);
        float iy = fmaf(ys[i], 512.0f, 511.5f);
        ixs[i] = ix;
        iys[i] = iy;
        int x0 = (int)floorf(ix);
        int y0 = (int)floorf(iy);
        unsigned xc = (unsigned)min(max(x0, 0), DIM - 2);
        unsigned yc = (unsigned)min(max(y0, 0), DIM - 2);
        q[i] = __ldg(gb + ((yc << 10) | xc));
    }
}

__device__ __forceinline__ void consume4(
    const float* ixs, const float* iys, const uint2* q, float* res)
{
#pragma unroll
    for (int i = 0; i < 4; ++i) {
        float ix = ixs[i];
        float iy = iys[i];
        float x0f = floorf(ix);
        float y0f = floorf(iy);
        float wx = ix - x0f;
        float wy = iy - y0f;
        int x0 = (int)x0f;
        int y0 = (int)y0f;

        bool xv0 = (unsigned)x0 < (unsigned)DIM;
        bool xv1 = (unsigned)(x0 + 1) < (unsigned)DIM;
        bool yv0 = (unsigned)y0 < (unsigned)DIM;
        bool yv1 = (unsigned)(y0 + 1) < (unsigned)DIM;

        float wxl = xv0 ? (1.0f - wx) : 0.0f;
        float wxr = xv1 ? wx : 0.0f;
        float wyt = yv0 ? (1.0f - wy) : 0.0f;
        float wyb = yv1 ? wy : 0.0f;

        float w1 = ((x0 == DIM - 1) ? wxl : 0.0f) + ((x0 == -1) ? 0.0f : wxr);
        float w0 = (wxl + wxr) - w1;
        float u1 = ((y0 == DIM - 1) ? wyt : 0.0f) + ((y0 == -1) ? 0.0f : wyb);
        float u0 = (wyt + wyb) - u1;

        float2 fA = __half22float2(*(__half2*)&q[i].x);   // row yc
        float2 fB = __half22float2(*(__half2*)&q[i].y);   // row yc+1

        float hA = fmaf(fA.y, w1, fA.x * w0);
        float hB = fmaf(fB.y, w1, fB.x * w0);
        res[i] = fmaf(hB, u1, hA * u0);
    }
}

__global__ __launch_bounds__(256, 6) void esm_main_kernel(
    const float* __restrict__ grid,
    float* __restrict__ out)
{
    unsigned tid = blockIdx.x * blockDim.x + threadIdx.x;
    unsigned p0 = tid * 8u;               // 8 pixels per thread (same batch)
    unsigned b = p0 >> 20;
    const uint2* __restrict__ gb = g_tiles + ((size_t)b << 20);

    const float4* g4 = (const float4*)(grid + (size_t)p0 * 2u);
    float4 ga = __ldg(g4);                // px 0,1
    float4 gc = __ldg(g4 + 1);            // px 2,3
    float4 ge = __ldg(g4 + 2);            // px 4,5
    float4 gf = __ldg(g4 + 3);            // px 6,7

    float ixA[4], iyA[4], ixB[4], iyB[4];
    uint2 qA[4], qB[4];

    issue4(gb, ga, gc, ixA, iyA, qA);     // group A gathers in flight
    issue4(gb, ge, gf, ixB, iyB, qB);     // group B gathers in flight

    float resA[4], resB[4];
    consume4(ixA, iyA, qA, resA);         // A latency covered by B issue
    consume4(ixB, iyB, qB, resB);

    float4 o0, o1;
    o0.x = resA[0]; o0.y = resA[1]; o0.z = resA[2]; o0.w = resA[3];
    o1.x = resB[0]; o1.y = resB[1]; o1.z = resB[2]; o1.w = resB[3];
    float4* ov = (float4*)(out + (size_t)p0);
    ov[0] = o0;
    ov[1] = o1;
}

extern "C" void kernel_launch(void* const* d_in, const int* in_sizes, int n_in,
                              void* d_out, int out_size)
{
    const float* img  = (const float*)d_in[0];   // source_depth
    const float* grid = (const float*)d_in[1];   // pr
    // d_in[2] (gt_map) unused.
    float* out = (float*)d_out;

    const unsigned threads = 256;
    esm_prepass_kernel<<<16u * 512u, threads>>>(img);
    esm_main_kernel<<<(TOTAL / 8u) / threads, threads>>>(grid, out);
}

// round 16
// speedup vs baseline: 1.1578x; 1.1578x over previous
#include <cuda_runtime.h>
#include <cuda_fp16.h>
#include <cstdint>

// ESMGridSample: bilinear grid_sample, zeros padding, align_corners=False.
// img:  [16, 1, 1024, 1024] f32   (d_in[0])
// grid: [16, 1024, 1024, 2] f32   (d_in[1])
// out:  [16, 1, 1024, 1024] f32
//
// R11 = R7 (best measured config: main 4 px/thread, 256 thr, regs 32,
// occ ~90%; prepass 4 tiles/thread) + L2 residency hints:
//   - grid loads:  __ldcs (stream, evict-first; read-once 128 MB)
//   - out stores:  __stcs (stream; write-once 64 MB)
// keeping L2 capacity for the per-batch 8 MB tile array that the random
// gathers re-touch.

#define DIM 1024
#define TOTAL (16u * 1024u * 1024u)

__device__ __align__(16) uint2 g_tiles[16u * 1024u * 1024u];   // 128 MB

__global__ __launch_bounds__(256) void esm_prepass_kernel(
    const float* __restrict__ img)
{
    // Thread handles 4 tiles: (xq..xq+3, y) of one batch.
    unsigned t = blockIdx.x * blockDim.x + threadIdx.x;
    unsigned xq = (t & 255u) * 4u;
    unsigned y  = (t >> 8) & 1023u;
    unsigned b  = t >> 18;

    const float* base = img + ((size_t)b << 20);
    unsigned y1 = min(y + 1u, 1023u);
    unsigned xe = min(xq + 4u, 1023u);

    const float* rA = base + ((size_t)y  << 10);
    const float* rB = base + ((size_t)y1 << 10);
    float4 a4 = __ldg((const float4*)(rA + xq));
    float4 b4 = __ldg((const float4*)(rB + xq));
    float ea = __ldg(rA + xe);
    float eb = __ldg(rB + xe);

    float at[5] = {a4.x, a4.y, a4.z, a4.w, ea};
    float bt[5] = {b4.x, b4.y, b4.z, b4.w, eb};

    uint32_t w[8];
#pragma unroll
    for (int j = 0; j < 4; ++j) {
        __half2 h0 = __floats2half2_rn(at[j], at[j + 1]);
        __half2 h1 = __floats2half2_rn(bt[j], bt[j + 1]);
        w[2 * j]     = *(uint32_t*)&h0;
        w[2 * j + 1] = *(uint32_t*)&h1;
    }
    // 4 tiles = 32 B contiguous, 32 B aligned (xq % 4 == 0).
    uint4* dst = (uint4*)(g_tiles + (((size_t)b << 20) | ((size_t)y << 10) | xq));
    dst[0] = make_uint4(w[0], w[1], w[2], w[3]);
    dst[1] = make_uint4(w[4], w[5], w[6], w[7]);
}

__device__ __forceinline__ float sample_one(
    const uint2* __restrict__ gb, float gx, float gy)
{
    float ix = fmaf(gx, 512.0f, 511.5f);
    float iy = fmaf(gy, 512.0f, 511.5f);
    float x0f = floorf(ix);
    float y0f = floorf(iy);
    float wx = ix - x0f;
    float wy = iy - y0f;
    int x0 = (int)x0f;
    int y0 = (int)y0f;

    bool xv0 = (unsigned)x0 < (unsigned)DIM;
    bool xv1 = (unsigned)(x0 + 1) < (unsigned)DIM;
    bool yv0 = (unsigned)y0 < (unsigned)DIM;
    bool yv1 = (unsigned)(y0 + 1) < (unsigned)DIM;

    float wxl = xv0 ? (1.0f - wx) : 0.0f;
    float wxr = xv1 ? wx : 0.0f;
    float wyt = yv0 ? (1.0f - wy) : 0.0f;
    float wyb = yv1 ? wy : 0.0f;

    // Tile-element weights; only the -1 / 1023 edges remap.
    float w1 = ((x0 == DIM - 1) ? wxl : 0.0f) + ((x0 == -1) ? 0.0f : wxr);
    float w0 = (wxl + wxr) - w1;
    float u1 = ((y0 == DIM - 1) ? wyt : 0.0f) + ((y0 == -1) ? 0.0f : wyb);
    float u0 = (wyt + wyb) - u1;

    unsigned xc = (unsigned)min(max(x0, 0), DIM - 2);
    unsigned yc = (unsigned)min(max(y0, 0), DIM - 2);

    uint2 q = __ldg(gb + ((yc << 10) | xc));
    float2 fA = __half22float2(*(__half2*)&q.x);   // row yc:   (xc, xc+1)
    float2 fB = __half22float2(*(__half2*)&q.y);   // row yc+1: (xc, xc+1)

    float hA = fmaf(fA.y, w1, fA.x * w0);
    float hB = fmaf(fB.y, w1, fB.x * w0);
    return fmaf(hB, u1, hA * u0);
}

__global__ __launch_bounds__(256) void esm_main_kernel(
    const float* __restrict__ grid,
    float* __restrict__ out)
{
    unsigned tid = blockIdx.x * blockDim.x + threadIdx.x;
    unsigned p0 = tid * 4u;               // 4 pixels per thread (same batch)
    unsigned b = p0 >> 20;
    const uint2* __restrict__ gb = g_tiles + ((size_t)b << 20);

    const float4* g4 = (const float4*)(grid + (size_t)p0 * 2u);
    float4 ga = __ldcs(g4);               // streaming: read-once grid
    float4 gc = __ldcs(g4 + 1);

    float r0 = sample_one(gb, ga.x, ga.y);
    float r1 = sample_one(gb, ga.z, ga.w);
    float r2 = sample_one(gb, gc.x, gc.y);
    float r3 = sample_one(gb, gc.z, gc.w);

    float4 o; o.x = r0; o.y = r1; o.z = r2; o.w = r3;
    __stcs((float4*)(out + (size_t)p0), o);   // streaming: write-once out
}

extern "C" void kernel_launch(void* const* d_in, const int* in_sizes, int n_in,
                              void* d_out, int out_size)
{
    const float* img  = (const float*)d_in[0];   // source_depth
    const float* grid = (const float*)d_in[1];   // pr
    // d_in[2] (gt_map) unused.
    float* out = (float*)d_out;

    const unsigned threads = 256;
    const unsigned prepass_threads = 16u * 1024u * 256u;   // 4,194,304
    esm_prepass_kernel<<<prepass_threads / threads, threads>>>(img);
    esm_main_kernel<<<(TOTAL / 4u) / threads, threads>>>(grid, out);
}